// round 16
// baseline (speedup 1.0000x reference)
#include <cuda_runtime.h>
#include <cuda_fp16.h>
#include <cstdint>

#define NN    512
#define H     128
#define L     4
#define NRBF  50
#define TBL   1024
#define NMOL  16
#define JT    16    // target nodes per msg block (2 halves of 8)
#define IS    32    // i-range splits (16 i's per block = 1 chunk)
#define CH    16    // i's per staged chunk
#define NT    4     // nodes per update block (2 per thread-half)
#define TPB   8     // table entries per sub-chunk
#define TSUB  4     // table sub-chunks per fused-prep block

typedef unsigned long long u64;

// ---- scratch (static __device__, no allocation) ----
__device__ float4 g_geo[NN * NN];        // [j][i] = (t_or_-1, dirx, diry, dirz), t = d*TBL/5
__device__ float4 g_tbl4[L][TBL][H / 2]; // [hp] = (p0@2hp, p0@2hp+1, p1@2hp, p1@2hp+1)/2
__device__ float  g_x[NN * H];
__device__ float  g_A[NN * H];           // 0.5*(x @ Wx + b1) (pre-halved)
__device__ float  g_S[NN * H];           // sum_i silu(pre[i,j])
__device__ float  g_deg[NN];             // # valid neighbors of j (layer-invariant)
__device__ float  g_pool[NMOL * H];

__device__ __forceinline__ float tanhf_approx(float x) {
    float t;
    asm("tanh.approx.f32 %0, %1;" : "=f"(t) : "f"(x));
    return t;
}
__device__ __forceinline__ float siluf(float v) {
    float s = 0.5f * v;
    return fmaf(s, tanhf_approx(s), s);
}
__device__ __forceinline__ uint32_t s2u(const void* p) {
    return (uint32_t)__cvta_generic_to_shared(p);
}
__device__ __forceinline__ u64 pk2(float lo, float hi) {
    u64 r; asm("mov.b64 %0, {%1, %2};" : "=l"(r) : "f"(lo), "f"(hi)); return r;
}
__device__ __forceinline__ void upk2(u64 v, float& lo, float& hi) {
    asm("mov.b64 {%0, %1}, %2;" : "=f"(lo), "=f"(hi) : "l"(v));
}
__device__ __forceinline__ u64 ffma2(u64 a, u64 b, u64 c) {
    u64 d; asm("fma.rn.f32x2 %0, %1, %2, %3;" : "=l"(d) : "l"(a), "l"(b), "l"(c)); return d;
}

// Fused prep:
//  blocks [0, NN):            pair geometry + degree (512 threads, thread per i)
//  blocks [NN, NN+NN/4):      layer-0 bootstrap (x=embed, A=0.5*(x@Wx0+b1), S=0)
//  blocks [NN+NN/4, +128):    psi tables — 4 sub-chunks of 8 entries share one
//                             smem-staged Wr (f32x2-packed output layout)
__global__ void __launch_bounds__(512)
k_prep(const float* __restrict__ pos,
       const int* __restrict__ an, const float* __restrict__ embed,
       const float* __restrict__ msg_w1, const float* __restrict__ msg_b1) {
    __shared__ int   cnt;
    __shared__ float xv[4][H];
    __shared__ float wr[NRBF * H];                 // 25.6 KB (table branch)
    __shared__ float e[TSUB][(TPB + 1) * NRBF];    // 7.2 KB
    int b = blockIdx.x;
    if (b < NN) {
        int j = b, i = threadIdx.x;
        float px = pos[j * 3 + 0], py = pos[j * 3 + 1], pz = pos[j * 3 + 2];
        float dx = pos[i * 3 + 0] - px;
        float dy = pos[i * 3 + 1] - py;
        float dz = pos[i * 3 + 2] - pz;
        float d  = sqrtf(dx * dx + dy * dy + dz * dz);
        float inv = 1.0f / fmaxf(d, 1e-8f);
        bool valid = (d < 5.0f) && (i != j);
        float t = valid ? d * ((float)TBL / 5.0f) : -1.0f;
        g_geo[j * NN + i] = make_float4(t, dx * inv, dy * inv, dz * inv);

        if (i == 0) cnt = 0;
        __syncthreads();
        unsigned m = __ballot_sync(0xffffffffu, valid);
        if ((i & 31) == 0) atomicAdd(&cnt, __popc(m));
        __syncthreads();
        if (i == 0) g_deg[j] = (float)cnt;
    } else if (b < NN + NN / 4) {
        int sub  = threadIdx.x >> 7;
        int h    = threadIdx.x & 127;
        int node = (b - NN) * 4 + sub;
        int a = an[node];
        a = a < 0 ? 0 : (a > 99 ? 99 : a);
        float xval = embed[a * H + h];
        g_x[node * H + h] = xval;
        xv[sub][h] = xval;
        __syncthreads();
        const float* Wx = msg_w1;        // layer 0, rows [0,H)
        float acc = msg_b1[h];
#pragma unroll 8
        for (int k = 0; k < H; k++)
            acc = fmaf(xv[sub][k], Wx[k * H + h], acc);
        g_A[node * H + h] = 0.5f * acc;
        g_S[node * H + h] = 0.0f;
    } else {
        int tb  = b - NN - NN / 4;       // 0..127
        int l   = tb >> 5;               // 4 layers x 32 chunk-groups
        int c4  = tb & 31;
        int sub = threadIdx.x >> 7;      // 0..3
        int h   = threadIdx.x & 127;
        int idx0 = (c4 * TSUB + sub) * TPB;
        const float* Wr = msg_w1 + l * 181 * H + H * H;   // rows [H, H+50)
        for (int t = threadIdx.x; t < NRBF * H; t += 512)
            wr[t] = __ldg(&Wr[t]);
        {
            float g = 5.0f / (float)TBL;
            for (int t = h; t < (TPB + 1) * NRBF; t += 128) {
                int j = t / NRBF, k = t - j * NRBF;
                float d = (float)(idx0 + j) * g;
                float c = 5.0f * (float)k / (float)(NRBF - 1);
                float u = d - c;
                e[sub][t] = expf(-u * u * 50.0f);
            }
        }
        __syncthreads();
        float p[TPB + 1];
#pragma unroll
        for (int j = 0; j <= TPB; j++) p[j] = 0.0f;
#pragma unroll
        for (int k = 0; k < NRBF; k++) {
            float w = wr[k * H + h];
#pragma unroll
            for (int j = 0; j <= TPB; j++)
                p[j] = fmaf(e[sub][j * NRBF + k], w, p[j]);
        }
        float po[TPB + 1];
#pragma unroll
        for (int j = 0; j <= TPB; j++)
            po[j] = __shfl_xor_sync(0xffffffffu, p[j], 1);
        if ((h & 1) == 0) {
            int hp = h >> 1;
#pragma unroll
            for (int q = 0; q < TPB; q++)
                g_tbl4[l][idx0 + q][hp] =
                    make_float4(0.5f * p[q], 0.5f * po[q], 0.5f * p[q + 1], 0.5f * po[q + 1]);
        }
    }
}

// message pass (round-13 proven version): smem-staged f32x2, h-pair per thread.
// Block: 128 threads = 64 h-pairs x 2 j-halves; covers JT=16 j's x CH=16 i's.
__global__ void __launch_bounds__(128)
k_msg(const float* __restrict__ msg_w1, int l) {
    int j0    = blockIdx.x * JT;
    int ibase = blockIdx.y * CH;
    int t  = threadIdx.x;
    int hp = t & 63;
    int jh = t >> 6;          // 0/1: which 8-j half this thread accumulates
    const float2* Wd2 = (const float2*)(msg_w1 + l * 181 * H + (H + NRBF) * H);
    float2 w0 = __ldg(&Wd2[hp]);
    float2 w1 = __ldg(&Wd2[64 + hp]);
    float2 w2 = __ldg(&Wd2[128 + hp]);
    u64 wd0 = pk2(0.5f * w0.x, 0.5f * w0.y);
    u64 wd1 = pk2(0.5f * w1.x, 0.5f * w1.y);
    u64 wd2p = pk2(0.5f * w2.x, 0.5f * w2.y);
    const float4* __restrict__ tb = &g_tbl4[l][0][0];

    __shared__ float4 sc1[JT * CH];      // (f, f, 1-f, 1-f)
    __shared__ float4 sc2[JT * CH];      // (dx, dx, dy, dy)
    __shared__ float2 sc3[JT * CH];      // (dz, dz)
    __shared__ int    sff[JT * CH];      // t0*64 or -1
    __shared__ u64    sa[CH][64];        // A as packed h-pairs

    {   // staging: 256 pairs / 128 threads = 2 each
#pragma unroll
        for (int r = 0; r < 2; r++) {
            int p = t + r * 128;
            int jj = p >> 4, ii = p & 15;
            float4 w = g_geo[(j0 + jj) * NN + ibase + ii];
            int t0 = (int)w.x;
            t0 = t0 < 0 ? 0 : t0;
            float f = w.x - (float)t0;
            sc1[p] = make_float4(f, f, 1.0f - f, 1.0f - f);
            sc2[p] = make_float4(w.y, w.y, w.z, w.z);
            sc3[p] = make_float2(w.w, w.w);
            sff[p] = w.x < 0.0f ? -1 : t0 * 64;
        }
        const float2* A2 = (const float2*)g_A;
#pragma unroll
        for (int r = 0; r < 8; r++) {
            int q = t + r * 128;
            int ii = q >> 6, hh = q & 63;
            float2 av = __ldg(&A2[(ibase + ii) * 64 + hh]);
            *(float2*)&sa[ii][hh] = av;
        }
    }
    __syncthreads();

    float accL[8], accH[8];
#pragma unroll
    for (int jj = 0; jj < 8; jj++) { accL[jj] = 0.0f; accH[jj] = 0.0f; }

    for (int ii = 0; ii < CH; ii++) {
        u64 a2 = sa[ii][hp];
#pragma unroll
        for (int jj = 0; jj < 8; jj++) {
            int p = ((jh << 3) + jj) * CH + ii;
            int off = sff[p];                        // uniform across warp
            if (off >= 0) {
                ulonglong2 c1 = *(const ulonglong2*)&sc1[p];
                ulonglong2 c2 = *(const ulonglong2*)&sc2[p];
                u64 c3 = *(const u64*)&sc3[p];
                ulonglong2 T = __ldg((const ulonglong2*)(tb + off + hp));
                u64 s = ffma2(c1.x, T.y, a2);        // f*p1 + a
                s = ffma2(c1.y, T.x, s);             // + (1-f)*p0
                s = ffma2(c2.x, wd0, s);             // + dx*wd0
                s = ffma2(c2.y, wd1, s);             // + dy*wd1
                s = ffma2(c3, wd2p, s);              // + dz*wd2
                float sl, sh;
                upk2(s, sl, sh);
                accL[jj] = fmaf(sl, tanhf_approx(sl), accL[jj] + sl);
                accH[jj] = fmaf(sh, tanhf_approx(sh), accH[jj] + sh);
            }
        }
    }
    int jbase = j0 + (jh << 3);
#pragma unroll
    for (int jj = 0; jj < 8; jj++) {
        atomicAdd(&g_S[(jbase + jj) * H + 2 * hp], accL[jj]);
        atomicAdd(&g_S[(jbase + jj) * H + 2 * hp + 1], accH[jj]);
    }
}

// ---- k_upd GEMM machinery: cp.async double-buffered smem weight tiles ----
#define ISSUE_CHUNK(Wbase, c, buf)                                            \
    {                                                                         \
        const float4* _wg = (const float4*)((Wbase) + (c) * 32 * H);          \
        uint32_t _sb = ws_u32 + (buf) * 16384 + tid * 16;                     \
        _Pragma("unroll")                                                     \
        for (int _i = 0; _i < 4; _i++)                                        \
            asm volatile("cp.async.ca.shared.global [%0], [%1], 16;"          \
                :: "r"(_sb + _i * 4096), "l"(_wg + _i * 256 + tid)            \
                : "memory");                                                  \
        asm volatile("cp.async.commit_group;" ::: "memory");                  \
    }

#define GEMMT(Wbase, s0, s1, acc0, acc1)                                      \
    ISSUE_CHUNK(Wbase, 0, 0);                                                 \
    _Pragma("unroll")                                                         \
    for (int _c = 0; _c < 4; _c++) {                                          \
        if (_c < 3) {                                                         \
            ISSUE_CHUNK(Wbase, _c + 1, (_c + 1) & 1);                         \
            asm volatile("cp.async.wait_group 1;" ::: "memory");              \
        } else {                                                              \
            asm volatile("cp.async.wait_group 0;" ::: "memory");              \
        }                                                                     \
        __syncthreads();                                                      \
        const float* _w = ws + (_c & 1) * 4096;                               \
        _Pragma("unroll")                                                     \
        for (int _t = 0; _t < 32; _t++) {                                     \
            float _wv = _w[_t * H + h];                                       \
            acc0 = fmaf((s0)[_c * 32 + _t], _wv, acc0);                       \
            acc1 = fmaf((s1)[_c * 32 + _t], _wv, acc1);                       \
        }                                                                     \
        __syncthreads();                                                      \
    }

__global__ void __launch_bounds__(256)
k_upd(const float* __restrict__ msg_w1, const float* __restrict__ msg_b1,
      const float* __restrict__ msg_w2, const float* __restrict__ msg_b2,
      const float* __restrict__ upd_w1, const float* __restrict__ upd_b1,
      const float* __restrict__ upd_w2, const float* __restrict__ upd_b2,
      const int* __restrict__ batch, int l) {
    int j0  = blockIdx.x * NT;
    int tid = threadIdx.x;
    int jb  = (tid >> 7) * 2;     // 0 or 2
    int h   = tid & 127;
    // zero the pooling buffer one launch before it's accumulated (l==3)
    if (l == 2 && blockIdx.x < NMOL && tid < H)
        g_pool[blockIdx.x * H + tid] = 0.0f;
    __shared__ float ws[2 * 32 * H];                       // 32 KB ring
    __shared__ float sv[NT][H], xv[NT][H], av[NT][H], hs[NT][H];
    uint32_t ws_u32 = s2u(ws);
    sv[jb    ][h] = g_S[(j0 + jb    ) * H + h];
    sv[jb + 1][h] = g_S[(j0 + jb + 1) * H + h];
    xv[jb    ][h] = g_x[(j0 + jb    ) * H + h];
    xv[jb + 1][h] = g_x[(j0 + jb + 1) * H + h];
    __syncthreads();
    {   // aggr = S @ W2 + deg * b2
        float b = msg_b2[l * H + h];
        float a0 = g_deg[j0 + jb] * b, a1 = g_deg[j0 + jb + 1] * b;
        const float* W2 = msg_w2 + l * H * H;
        GEMMT(W2, sv[jb], sv[jb + 1], a0, a1)
        av[jb][h] = a0; av[jb + 1][h] = a1;
    }
    {   // hs = silu([x, aggr] @ U1 + ub1)
        float b = upd_b1[l * H + h];
        float a0 = b, a1 = b;
        const float* U1  = upd_w1 + l * 2 * H * H;
        const float* U1b = U1 + H * H;
        GEMMT(U1,  xv[jb], xv[jb + 1], a0, a1)
        GEMMT(U1b, av[jb], av[jb + 1], a0, a1)
        hs[jb][h] = siluf(a0); hs[jb + 1][h] = siluf(a1);
    }
    __syncthreads();
    float xn0, xn1;
    {   // x_new = x + hs @ U2 + ub2
        float b = upd_b2[l * H + h];
        float a0 = b, a1 = b;
        const float* U2 = upd_w2 + l * H * H;
        GEMMT(U2, hs[jb], hs[jb + 1], a0, a1)
        xn0 = xv[jb][h] + a0;
        xn1 = xv[jb + 1][h] + a1;
        g_x[(j0 + jb    ) * H + h] = xn0;
        g_x[(j0 + jb + 1) * H + h] = xn1;
    }
    __syncthreads();
    if (l + 1 < L) {
        // A_next = 0.5*(x_new @ Wx_{l+1} + b1_{l+1}) ; zero S
        sv[jb][h] = xn0; sv[jb + 1][h] = xn1;
        const float* Wx = msg_w1 + (l + 1) * 181 * H;
        float b = msg_b1[(l + 1) * H + h];
        float a0 = b, a1 = b;
        GEMMT(Wx, sv[jb], sv[jb + 1], a0, a1)
        g_A[(j0 + jb    ) * H + h] = 0.5f * a0;
        g_A[(j0 + jb + 1) * H + h] = 0.5f * a1;
        g_S[(j0 + jb    ) * H + h] = 0.0f;
        g_S[(j0 + jb + 1) * H + h] = 0.0f;
    } else {
        // last layer: pool directly
        atomicAdd(&g_pool[batch[j0 + jb    ] * H + h], xn0);
        atomicAdd(&g_pool[batch[j0 + jb + 1] * H + h], xn1);
    }
}

// mean (count computed inline from batch) + output MLP
__global__ void k_head(const int* __restrict__ batch,
                       const float* __restrict__ ow1, const float* __restrict__ ob1,
                       const float* __restrict__ ow2, const float* __restrict__ ob2,
                       float* __restrict__ out) {
    int m = blockIdx.x, h = threadIdx.x;
    __shared__ float pv[H];
    __shared__ float hv[64];
    __shared__ int   scnt;
    if (h == 0) scnt = 0;
    __syncthreads();
    int local = 0;
#pragma unroll
    for (int i = h; i < NN; i += H) local += (batch[i] == m) ? 1 : 0;
#pragma unroll
    for (int o = 16; o > 0; o >>= 1)
        local += __shfl_down_sync(0xffffffffu, local, o);
    if ((h & 31) == 0) atomicAdd(&scnt, local);
    __syncthreads();
    pv[h] = g_pool[m * H + h] / fmaxf((float)scnt, 1.0f);
    __syncthreads();
    if (h < 64) {
        float acc = ob1[h];
#pragma unroll 8
        for (int k = 0; k < H; k++) acc = fmaf(pv[k], ow1[k * 64 + h], acc);
        float s = 0.5f * acc;
        hv[h] = fmaf(s, tanhf_approx(s), s);
    }
    __syncthreads();
    if (h == 0) {
        float acc = ob2[0];
#pragma unroll
        for (int k = 0; k < 64; k++) acc = fmaf(hv[k], ow2[k], acc);
        out[m] = acc;
    }
}

extern "C" void kernel_launch(void* const* d_in, const int* in_sizes, int n_in,
                              void* d_out, int out_size) {
    const int*   an     = (const int*)  d_in[0];
    const float* pos    = (const float*)d_in[1];
    const int*   batch  = (const int*)  d_in[2];
    const float* embed  = (const float*)d_in[3];
    const float* msg_w1 = (const float*)d_in[4];
    const float* msg_b1 = (const float*)d_in[5];
    const float* msg_w2 = (const float*)d_in[6];
    const float* msg_b2 = (const float*)d_in[7];
    const float* upd_w1 = (const float*)d_in[8];
    const float* upd_b1 = (const float*)d_in[9];
    const float* upd_w2 = (const float*)d_in[10];
    const float* upd_b2 = (const float*)d_in[11];
    const float* ow1    = (const float*)d_in[12];
    const float* ob1    = (const float*)d_in[13];
    const float* ow2    = (const float*)d_in[14];
    const float* ob2    = (const float*)d_in[15];
    float* out = (float*)d_out;

    // launch #0: fused prep (geometry + bootstrap + tables)
    k_prep<<<NN + NN / 4 + (TBL / (TPB * TSUB)) * L, 512>>>(pos, an, embed, msg_w1, msg_b1);
    // launches #1..#8; #5 is k_msg(l=2) -> captured by ncu (-s 5 -c 1)
    for (int l = 0; l < L; l++) {
        k_msg<<<dim3(NN / JT, IS), 128>>>(msg_w1, l);
        k_upd<<<NN / NT, 256>>>(msg_w1, msg_b1, msg_w2, msg_b2,
                                upd_w1, upd_b1, upd_w2, upd_b2, batch, l);
    }
    k_head<<<NMOL, H>>>(batch, ow1, ob1, ow2, ob2, out);
}

// round 17
// speedup vs baseline: 1.5771x; 1.5771x over previous
#include <cuda_runtime.h>
#include <cuda_fp16.h>
#include <cstdint>

#define NN    512
#define H     128
#define L     4
#define NRBF  50
#define TBL   1024
#define NMOL  16
#define JT    16    // target nodes per msg block (2 halves of 8)
#define IS    64    // i-range splits (8 i's per block)
#define CH    8     // i's per staged chunk
#define NT    4     // nodes per update block (2 per thread-half)
#define TPB   8     // table entries per k_table block

typedef unsigned long long u64;

// ---- scratch (static __device__, no allocation) ----
__device__ float4 g_geo[NN * NN];        // [j][i] = (t_or_-1, dirx, diry, dirz), t = d*TBL/5
__device__ float4 g_tbl4[L][TBL][H / 2]; // [hp] = (p0@2hp, p0@2hp+1, p1@2hp, p1@2hp+1)/2
__device__ float  g_x[NN * H];
__device__ float  g_A[NN * H];           // 0.5*(x @ Wx + b1) (pre-halved)
__device__ float  g_S[NN * H];           // sum_i silu(pre[i,j])
__device__ float  g_deg[NN];             // # valid neighbors of j (layer-invariant)
__device__ float  g_pool[NMOL * H];
__device__ float  g_cntm[NMOL];

__device__ __forceinline__ float tanhf_approx(float x) {
    float t;
    asm("tanh.approx.f32 %0, %1;" : "=f"(t) : "f"(x));
    return t;
}
__device__ __forceinline__ float siluf(float v) {
    float s = 0.5f * v;
    return fmaf(s, tanhf_approx(s), s);
}
__device__ __forceinline__ uint32_t s2u(const void* p) {
    return (uint32_t)__cvta_generic_to_shared(p);
}
__device__ __forceinline__ u64 pk2(float lo, float hi) {
    u64 r; asm("mov.b64 %0, {%1, %2};" : "=l"(r) : "f"(lo), "f"(hi)); return r;
}
__device__ __forceinline__ void upk2(u64 v, float& lo, float& hi) {
    asm("mov.b64 {%0, %1}, %2;" : "=f"(lo), "=f"(hi) : "l"(v));
}
__device__ __forceinline__ u64 ffma2(u64 a, u64 b, u64 c) {
    u64 d; asm("fma.rn.f32x2 %0, %1, %2, %3;" : "=l"(d) : "l"(a), "l"(b), "l"(c)); return d;
}

// psi tables: block computes TPB=8 consecutive idx, Wr staged once in smem.
// Packed for f32x2 h-pairs. Also zeroes pool/cntm.
__global__ void __launch_bounds__(128)
k_table(const float* __restrict__ msg_w1) {
    int idx0 = blockIdx.x * TPB;     // 0..TBL-8
    int l    = blockIdx.y;
    int h    = threadIdx.x;
    if (idx0 == 0 && l == 0) {
        if (h < NMOL) g_cntm[h] = 0.0f;
#pragma unroll
        for (int m = 0; m < NMOL; m++) g_pool[m * H + h] = 0.0f;
    }
    __shared__ float wr[NRBF * H];       // 25.6 KB
    __shared__ float e[(TPB + 1) * NRBF];
    const float* Wr = msg_w1 + l * 181 * H + H * H;   // rows [H, H+50)
#pragma unroll
    for (int i = 0; i < NRBF; i++)
        wr[i * H + h] = __ldg(&Wr[i * H + h]);
    {
        float g = 5.0f / (float)TBL;
        for (int t = h; t < (TPB + 1) * NRBF; t += 128) {
            int j = t / NRBF, k = t - j * NRBF;
            float d = (float)(idx0 + j) * g;
            float c = 5.0f * (float)k / (float)(NRBF - 1);
            float u = d - c;
            e[t] = expf(-u * u * 50.0f);
        }
    }
    __syncthreads();
    float p[TPB + 1];
#pragma unroll
    for (int j = 0; j <= TPB; j++) p[j] = 0.0f;
#pragma unroll
    for (int k = 0; k < NRBF; k++) {
        float w = wr[k * H + h];
#pragma unroll
        for (int j = 0; j <= TPB; j++)
            p[j] = fmaf(e[j * NRBF + k], w, p[j]);
    }
    float po[TPB + 1];
#pragma unroll
    for (int j = 0; j <= TPB; j++)
        po[j] = __shfl_xor_sync(0xffffffffu, p[j], 1);
    if ((h & 1) == 0) {
        int hp = h >> 1;
#pragma unroll
        for (int q = 0; q < TPB; q++)
            g_tbl4[l][idx0 + q][hp] =
                make_float4(0.5f * p[q], 0.5f * po[q], 0.5f * p[q + 1], 0.5f * po[q + 1]);
    }
}

// merged: blocks [0,NN) pair geometry + degree; blocks [NN, NN+NN/4) layer-0
// bootstrap (x = embed, A = 0.5*(x@Wx0+b1), S = 0, atoms/mol count).
__global__ void __launch_bounds__(512)
k_prep(const float* __restrict__ pos,
       const int* __restrict__ an, const float* __restrict__ embed,
       const float* __restrict__ msg_w1, const float* __restrict__ msg_b1,
       const int* __restrict__ batch) {
    __shared__ int   cnt;
    __shared__ float xv[4][H];
    if (blockIdx.x < NN) {
        int j = blockIdx.x, i = threadIdx.x;
        float px = pos[j * 3 + 0], py = pos[j * 3 + 1], pz = pos[j * 3 + 2];
        float dx = pos[i * 3 + 0] - px;
        float dy = pos[i * 3 + 1] - py;
        float dz = pos[i * 3 + 2] - pz;
        float d  = sqrtf(dx * dx + dy * dy + dz * dz);
        float inv = 1.0f / fmaxf(d, 1e-8f);
        bool valid = (d < 5.0f) && (i != j);
        float t = valid ? d * ((float)TBL / 5.0f) : -1.0f;
        g_geo[j * NN + i] = make_float4(t, dx * inv, dy * inv, dz * inv);

        if (i == 0) cnt = 0;
        __syncthreads();
        unsigned m = __ballot_sync(0xffffffffu, valid);
        if ((i & 31) == 0) atomicAdd(&cnt, __popc(m));
        __syncthreads();
        if (i == 0) g_deg[j] = (float)cnt;
    } else {
        int sub  = threadIdx.x >> 7;
        int h    = threadIdx.x & 127;
        int node = (blockIdx.x - NN) * 4 + sub;
        int a = an[node];
        a = a < 0 ? 0 : (a > 99 ? 99 : a);
        float xval = embed[a * H + h];
        g_x[node * H + h] = xval;
        xv[sub][h] = xval;
        __syncthreads();
        const float* Wx = msg_w1;        // layer 0, rows [0,H)
        float acc = msg_b1[h];
#pragma unroll 8
        for (int k = 0; k < H; k++)
            acc = fmaf(xv[sub][k], Wx[k * H + h], acc);
        g_A[node * H + h] = 0.5f * acc;
        g_S[node * H + h] = 0.0f;
        if (h == 0) atomicAdd(&g_cntm[batch[node]], 1.0f);
    }
}

// message pass: smem-staged f32x2, h-pair per thread, CH=8 i's per block.
// Block: 128 threads = 64 h-pairs x 2 j-halves; covers JT=16 j's x CH=8 i's.
__global__ void __launch_bounds__(128)
k_msg(const float* __restrict__ msg_w1, int l) {
    int j0    = blockIdx.x * JT;
    int ibase = blockIdx.y * CH;
    int t  = threadIdx.x;
    int hp = t & 63;
    int jh = t >> 6;          // 0/1: which 8-j half this thread accumulates
    const float2* Wd2 = (const float2*)(msg_w1 + l * 181 * H + (H + NRBF) * H);
    float2 w0 = __ldg(&Wd2[hp]);
    float2 w1 = __ldg(&Wd2[64 + hp]);
    float2 w2 = __ldg(&Wd2[128 + hp]);
    u64 wd0 = pk2(0.5f * w0.x, 0.5f * w0.y);
    u64 wd1 = pk2(0.5f * w1.x, 0.5f * w1.y);
    u64 wd2p = pk2(0.5f * w2.x, 0.5f * w2.y);
    const float4* __restrict__ tb = &g_tbl4[l][0][0];

    __shared__ float4 sc1[JT * CH];      // (f, f, 1-f, 1-f)
    __shared__ float4 sc2[JT * CH];      // (dx, dx, dy, dy)
    __shared__ float2 sc3[JT * CH];      // (dz, dz)
    __shared__ int    sff[JT * CH];      // t0*64 or -1
    __shared__ u64    sa[CH][64];        // A as packed h-pairs

    {   // staging: 128 pairs / 128 threads = 1 each
        int p = t;
        int jj = p >> 3, ii = p & 7;
        float4 w = g_geo[(j0 + jj) * NN + ibase + ii];
        int t0 = (int)w.x;
        t0 = t0 < 0 ? 0 : t0;
        float f = w.x - (float)t0;
        sc1[p] = make_float4(f, f, 1.0f - f, 1.0f - f);
        sc2[p] = make_float4(w.y, w.y, w.z, w.z);
        sc3[p] = make_float2(w.w, w.w);
        sff[p] = w.x < 0.0f ? -1 : t0 * 64;
        const float2* A2 = (const float2*)g_A;
#pragma unroll
        for (int r = 0; r < 4; r++) {
            int q = t + r * 128;
            int ii2 = q >> 6, hh = q & 63;
            float2 av = __ldg(&A2[(ibase + ii2) * 64 + hh]);
            *(float2*)&sa[ii2][hh] = av;
        }
    }
    __syncthreads();

    float accL[8], accH[8];
#pragma unroll
    for (int jj = 0; jj < 8; jj++) { accL[jj] = 0.0f; accH[jj] = 0.0f; }

    for (int ii = 0; ii < CH; ii++) {
        u64 a2 = sa[ii][hp];
#pragma unroll
        for (int jj = 0; jj < 8; jj++) {
            int p = ((jh << 3) + jj) * CH + ii;
            int off = sff[p];                        // uniform across warp
            if (off >= 0) {
                ulonglong2 c1 = *(const ulonglong2*)&sc1[p];
                ulonglong2 c2 = *(const ulonglong2*)&sc2[p];
                u64 c3 = *(const u64*)&sc3[p];
                ulonglong2 T = __ldg((const ulonglong2*)(tb + off + hp));
                u64 s = ffma2(c1.x, T.y, a2);        // f*p1 + a
                s = ffma2(c1.y, T.x, s);             // + (1-f)*p0
                s = ffma2(c2.x, wd0, s);             // + dx*wd0
                s = ffma2(c2.y, wd1, s);             // + dy*wd1
                s = ffma2(c3, wd2p, s);              // + dz*wd2
                float sl, sh;
                upk2(s, sl, sh);
                accL[jj] = fmaf(sl, tanhf_approx(sl), accL[jj] + sl);
                accH[jj] = fmaf(sh, tanhf_approx(sh), accH[jj] + sh);
            }
        }
    }
    int jbase = j0 + (jh << 3);
#pragma unroll
    for (int jj = 0; jj < 8; jj++) {
        atomicAdd(&g_S[(jbase + jj) * H + 2 * hp], accL[jj]);
        atomicAdd(&g_S[(jbase + jj) * H + 2 * hp + 1], accH[jj]);
    }
}

// ---- k_upd GEMM machinery: cp.async double-buffered smem weight tiles ----
#define ISSUE_CHUNK(Wbase, c, buf)                                            \
    {                                                                         \
        const float4* _wg = (const float4*)((Wbase) + (c) * 32 * H);          \
        uint32_t _sb = ws_u32 + (buf) * 16384 + tid * 16;                     \
        _Pragma("unroll")                                                     \
        for (int _i = 0; _i < 4; _i++)                                        \
            asm volatile("cp.async.ca.shared.global [%0], [%1], 16;"          \
                :: "r"(_sb + _i * 4096), "l"(_wg + _i * 256 + tid)            \
                : "memory");                                                  \
        asm volatile("cp.async.commit_group;" ::: "memory");                  \
    }

#define GEMMT(Wbase, s0, s1, acc0, acc1)                                      \
    ISSUE_CHUNK(Wbase, 0, 0);                                                 \
    _Pragma("unroll")                                                         \
    for (int _c = 0; _c < 4; _c++) {                                          \
        if (_c < 3) {                                                         \
            ISSUE_CHUNK(Wbase, _c + 1, (_c + 1) & 1);                         \
            asm volatile("cp.async.wait_group 1;" ::: "memory");              \
        } else {                                                              \
            asm volatile("cp.async.wait_group 0;" ::: "memory");              \
        }                                                                     \
        __syncthreads();                                                      \
        const float* _w = ws + (_c & 1) * 4096;                               \
        _Pragma("unroll")                                                     \
        for (int _t = 0; _t < 32; _t++) {                                     \
            float _wv = _w[_t * H + h];                                       \
            acc0 = fmaf((s0)[_c * 32 + _t], _wv, acc0);                       \
            acc1 = fmaf((s1)[_c * 32 + _t], _wv, acc1);                       \
        }                                                                     \
        __syncthreads();                                                      \
    }

__global__ void __launch_bounds__(256)
k_upd(const float* __restrict__ msg_w1, const float* __restrict__ msg_b1,
      const float* __restrict__ msg_w2, const float* __restrict__ msg_b2,
      const float* __restrict__ upd_w1, const float* __restrict__ upd_b1,
      const float* __restrict__ upd_w2, const float* __restrict__ upd_b2,
      const int* __restrict__ batch, int l) {
    int j0  = blockIdx.x * NT;
    int tid = threadIdx.x;
    int jb  = (tid >> 7) * 2;     // 0 or 2
    int h   = tid & 127;
    __shared__ float ws[2 * 32 * H];                       // 32 KB ring
    __shared__ float sv[NT][H], xv[NT][H], av[NT][H], hs[NT][H];
    uint32_t ws_u32 = s2u(ws);
    sv[jb    ][h] = g_S[(j0 + jb    ) * H + h];
    sv[jb + 1][h] = g_S[(j0 + jb + 1) * H + h];
    xv[jb    ][h] = g_x[(j0 + jb    ) * H + h];
    xv[jb + 1][h] = g_x[(j0 + jb + 1) * H + h];
    __syncthreads();
    {   // aggr = S @ W2 + deg * b2
        float b = msg_b2[l * H + h];
        float a0 = g_deg[j0 + jb] * b, a1 = g_deg[j0 + jb + 1] * b;
        const float* W2 = msg_w2 + l * H * H;
        GEMMT(W2, sv[jb], sv[jb + 1], a0, a1)
        av[jb][h] = a0; av[jb + 1][h] = a1;
    }
    {   // hs = silu([x, aggr] @ U1 + ub1)
        float b = upd_b1[l * H + h];
        float a0 = b, a1 = b;
        const float* U1  = upd_w1 + l * 2 * H * H;
        const float* U1b = U1 + H * H;
        GEMMT(U1,  xv[jb], xv[jb + 1], a0, a1)
        GEMMT(U1b, av[jb], av[jb + 1], a0, a1)
        hs[jb][h] = siluf(a0); hs[jb + 1][h] = siluf(a1);
    }
    __syncthreads();
    float xn0, xn1;
    {   // x_new = x + hs @ U2 + ub2
        float b = upd_b2[l * H + h];
        float a0 = b, a1 = b;
        const float* U2 = upd_w2 + l * H * H;
        GEMMT(U2, hs[jb], hs[jb + 1], a0, a1)
        xn0 = xv[jb][h] + a0;
        xn1 = xv[jb + 1][h] + a1;
        g_x[(j0 + jb    ) * H + h] = xn0;
        g_x[(j0 + jb + 1) * H + h] = xn1;
    }
    __syncthreads();
    if (l + 1 < L) {
        // A_next = 0.5*(x_new @ Wx_{l+1} + b1_{l+1}) ; zero S
        sv[jb][h] = xn0; sv[jb + 1][h] = xn1;
        const float* Wx = msg_w1 + (l + 1) * 181 * H;
        float b = msg_b1[(l + 1) * H + h];
        float a0 = b, a1 = b;
        GEMMT(Wx, sv[jb], sv[jb + 1], a0, a1)
        g_A[(j0 + jb    ) * H + h] = 0.5f * a0;
        g_A[(j0 + jb + 1) * H + h] = 0.5f * a1;
        g_S[(j0 + jb    ) * H + h] = 0.0f;
        g_S[(j0 + jb + 1) * H + h] = 0.0f;
    } else {
        // last layer: pool directly
        atomicAdd(&g_pool[batch[j0 + jb    ] * H + h], xn0);
        atomicAdd(&g_pool[batch[j0 + jb + 1] * H + h], xn1);
    }
}

// mean + output MLP
__global__ void k_head(const float* __restrict__ ow1, const float* __restrict__ ob1,
                       const float* __restrict__ ow2, const float* __restrict__ ob2,
                       float* __restrict__ out) {
    int m = blockIdx.x, h = threadIdx.x;
    __shared__ float pv[H];
    __shared__ float hv[64];
    pv[h] = g_pool[m * H + h] / fmaxf(g_cntm[m], 1.0f);
    __syncthreads();
    if (h < 64) {
        float acc = ob1[h];
#pragma unroll 8
        for (int k = 0; k < H; k++) acc = fmaf(pv[k], ow1[k * 64 + h], acc);
        float s = 0.5f * acc;
        hv[h] = fmaf(s, tanhf_approx(s), s);
    }
    __syncthreads();
    if (h == 0) {
        float acc = ob2[0];
#pragma unroll
        for (int k = 0; k < 64; k++) acc = fmaf(hv[k], ow2[k], acc);
        out[m] = acc;
    }
}

extern "C" void kernel_launch(void* const* d_in, const int* in_sizes, int n_in,
                              void* d_out, int out_size) {
    const int*   an     = (const int*)  d_in[0];
    const float* pos    = (const float*)d_in[1];
    const int*   batch  = (const int*)  d_in[2];
    const float* embed  = (const float*)d_in[3];
    const float* msg_w1 = (const float*)d_in[4];
    const float* msg_b1 = (const float*)d_in[5];
    const float* msg_w2 = (const float*)d_in[6];
    const float* msg_b2 = (const float*)d_in[7];
    const float* upd_w1 = (const float*)d_in[8];
    const float* upd_b1 = (const float*)d_in[9];
    const float* upd_w2 = (const float*)d_in[10];
    const float* upd_b2 = (const float*)d_in[11];
    const float* ow1    = (const float*)d_in[12];
    const float* ob1    = (const float*)d_in[13];
    const float* ow2    = (const float*)d_in[14];
    const float* ob2    = (const float*)d_in[15];
    float* out = (float*)d_out;

    k_table<<<dim3(TBL / TPB, L), H>>>(msg_w1);
    k_prep<<<NN + NN / 4, 512>>>(pos, an, embed, msg_w1, msg_b1, batch);
    for (int l = 0; l < L; l++) {
        k_msg<<<dim3(NN / JT, IS), 128>>>(msg_w1, l);
        k_upd<<<NN / NT, 256>>>(msg_w1, msg_b1, msg_w2, msg_b2,
                                upd_w1, upd_b1, upd_w2, upd_b2, batch, l);
    }
    k_head<<<NMOL, H>>>(ow1, ob1, ow2, ob2, out);
}